// round 10
// baseline (speedup 1.0000x reference)
#include <cuda_runtime.h>
#include <cuda_bf16.h>
#include <cstdint>

#define NB   2048
#define NN   64
#define NPAD 132
#define NEG_BIG (-9000000000000000.0f)

#define OFF_S    0          // 64*132 fp32
#define OFF_X    8448       // persistent S bf16 hi/lo tile (34816B)
#define OFF_Y    17152      // ATT tile | gate W staging
#define OFF_A    25856      // AKT scale table (512 u32)
#define OFF_STAR 26368
#define OFF_V2A  26496
#define OFF_V2B  26624
#define OFF_MS   26752
#define OFF_BR   26816
#define OFF_PA   26880
#define OFF_PB   27008
#define SM_FLOATS 27136
#define SM_BYTES (SM_FLOATS*4 + 64*68)

#define TS    272
#define THALF 17408
#define ATT_S 144
#define ATT_HALF 9216
#define GWS   144
#define GWHALF (128*144)

__device__ float g_M1[16384];   // q1 @ k1^T  (row-major)
__device__ float g_M2[16384];   // k2 @ q2^T  (row-major)

__device__ __forceinline__ uint32_t smem_u32(const void* p) {
    uint32_t a;
    asm("{ .reg .u64 t; cvta.to.shared.u64 t, %1; cvt.u32.u64 %0, t; }" : "=r"(a) : "l"(p));
    return a;
}
__device__ __forceinline__ uint32_t pack_bf2(__nv_bfloat16 a, __nv_bfloat16 b) {
    __nv_bfloat162 v = __halves2bfloat162(a, b);
    return *reinterpret_cast<uint32_t*>(&v);
}
__device__ __forceinline__ void cvt_hilo(float2 v, uint32_t& hi, uint32_t& lo) {
    __nv_bfloat16 h0 = __float2bfloat16_rn(v.x), h1 = __float2bfloat16_rn(v.y);
    hi = pack_bf2(h0, h1);
    lo = pack_bf2(__float2bfloat16_rn(v.x - __bfloat162float(h0)),
                  __float2bfloat16_rn(v.y - __bfloat162float(h1)));
}

#define LDSM4(r, addr) \
    asm volatile("ldmatrix.sync.aligned.m8n8.x4.shared.b16 {%0,%1,%2,%3}, [%4];" \
        : "=r"((r)[0]), "=r"((r)[1]), "=r"((r)[2]), "=r"((r)[3]) : "r"(addr))
#define LDSM2(r0, r1, addr) \
    asm volatile("ldmatrix.sync.aligned.m8n8.x2.shared.b16 {%0,%1}, [%2];" \
        : "=r"(r0), "=r"(r1) : "r"(addr))
#define LDSM2T(r0, r1, addr) \
    asm volatile("ldmatrix.sync.aligned.m8n8.x2.trans.shared.b16 {%0,%1}, [%2];" \
        : "=r"(r0), "=r"(r1) : "r"(addr))
#define MMA16816(c0,c1,c2,c3, a, b0,b1) \
    asm volatile("mma.sync.aligned.m16n8k16.row.col.f32.bf16.bf16.f32 " \
        "{%0,%1,%2,%3}, {%4,%5,%6,%7}, {%8,%9}, {%0,%1,%2,%3};" \
        : "+f"(c0), "+f"(c1), "+f"(c2), "+f"(c3) \
        : "r"((a)[0]), "r"((a)[1]), "r"((a)[2]), "r"((a)[3]), "r"(b0), "r"(b1))
#define FMA16X2(d,a,b,c) \
    asm("fma.rn.bf16x2 %0, %1, %2, %3;" : "=r"(d) : "r"(a), "r"(b), "r"(c))

__device__ __forceinline__ void build_tile(const float* S, char* tile, int tid) {
    for (int p = tid; p < 4096; p += 256) {
        int row = p >> 6, d = (p & 63) << 1;
        float2 sv = *reinterpret_cast<const float2*>(&S[row * NPAD + d]);
        uint32_t hi, lo;
        cvt_hilo(sv, hi, lo);
        int off = row * TS + d * 2;
        *reinterpret_cast<uint32_t*>(tile + off)         = hi;
        *reinterpret_cast<uint32_t*>(tile + THALF + off) = lo;
    }
}

__global__ void prep_kernel(const float* __restrict__ q1, const float* __restrict__ k1,
                            const float* __restrict__ q2, const float* __restrict__ k2) {
    int o = blockIdx.x * 256 + threadIdx.x;
    int m = o >> 14, idx = o & 16383;
    int t = idx >> 7, c = idx & 127;
    const float* X = m ? k2 : q1;
    const float* Y = m ? q2 : k1;
    float acc = 0.f;
    const float4* xr = reinterpret_cast<const float4*>(X + t * 128);
    const float4* yr = reinterpret_cast<const float4*>(Y + c * 128);
    #pragma unroll 8
    for (int d = 0; d < 32; d++) {
        float4 xv = xr[d], yv = yr[d];
        acc += xv.x * yv.x + xv.y * yv.y + xv.z * yv.z + xv.w * yv.w;
    }
    (m ? g_M2 : g_M1)[t * 128 + c] = acc;    // row-major
}

__global__ void __launch_bounds__(256, 2)
star_agg_kernel(const float* __restrict__ hidden, const int* __restrict__ adj,
                const float* __restrict__ mask,
                const float* __restrict__ a0, const float* __restrict__ a1,
                const float* __restrict__ a2, const float* __restrict__ a3,
                const float* __restrict__ wlin,
                float* __restrict__ outp, float* __restrict__ starp)
{
    extern __shared__ float sm[];
    float* S    = sm + OFF_S;
    float* AKTf = sm + OFF_A;
    float* STAR = sm + OFF_STAR;
    float* V2A  = sm + OFF_V2A;
    float* V2B  = sm + OFF_V2B;
    float* MS   = sm + OFF_MS;
    float* BR   = sm + OFF_BR;
    float* PA   = sm + OFF_PA;
    float* PB   = sm + OFF_PB;
    char*  XT   = (char*)(sm + OFF_X);
    char*  YT   = (char*)(sm + OFF_Y);
    uint32_t* AKT = (uint32_t*)AKTf;
    unsigned char* ADJ = (unsigned char*)(sm + SM_FLOATS);

    const int tid = threadIdx.x, lane = tid & 31, warp = tid >> 5, b = blockIdx.x;
    const uint32_t smb = smem_u32(sm);
    const uint32_t XH = smb + OFF_X * 4;
    const uint32_t YH = smb + OFF_Y * 4;
    const float* hg = hidden + (size_t)b * (NN * 128);
    const int*   ag = adj + (size_t)b * (NN * NN);
    const uint32_t Z16 = 0;

    for (int idx = tid; idx < NN * 32; idx += 256) {
        int i = idx >> 5, c4 = (idx & 31) << 2;
        *reinterpret_cast<float4*>(&S[i * NPAD + c4]) = reinterpret_cast<const float4*>(hg)[idx];
    }
    for (int idx = tid; idx < NN * NN; idx += 256)
        ADJ[(idx >> 6) * 68 + (idx & 63)] = (unsigned char)ag[idx];
    // AKT scale table: per (k,kt,l2): [akh(d0), akh(d0+8), akl(d0), akl(d0+8)] as bf16x2
    for (int e = tid; e < 512; e += 256) {
        int q = e & 3, l2 = (e >> 2) & 3, kt = (e >> 4) & 7, k = e >> 7;
        int d = kt * 16 + l2 * 2 + ((q & 1) ? 8 : 0);
        const float* ak = (k == 0) ? a0 : (k == 1) ? a1 : (k == 2) ? a2 : a3;
        uint32_t hi, lo;
        cvt_hilo(make_float2(ak[d], ak[d + 1]), hi, lo);
        AKT[e] = (q < 2) ? hi : lo;
    }
    if (tid < 64) MS[tid] = mask[b * NN + tid];
    __syncthreads();
    build_tile(S, XT, tid);
    if (tid < 128) {
        float acc = 0.f, msum = 0.f;
        #pragma unroll 8
        for (int i = 0; i < NN; i++) { acc += S[i * NPAD + tid] * MS[i]; msum += MS[i]; }
        STAR[tid] = acc / msum;
    }
    __syncthreads();

    const float RSQ = 0.088388347648318447f;
    const int mstrip = warp & 3, nhalf = warp >> 2;
    const int R0 = mstrip * 16, N0 = nhalf * 32;
    const int g = lane >> 2, i0 = R0 + g;
    const int lsel = lane & 15;
    const int m4 = lane >> 3;
    const uint32_t abase = XH + (uint32_t)(R0 + (lane & 7) + ((m4 & 1) << 3)) * TS
                         + ((m4 >> 1) << 4);
    const uint32_t xbbase = XH + (uint32_t)(N0 + (lsel & 7)) * TS + ((lsel >> 3) << 4);

    for (int step = 0; step < 2; step++) {
        // ===== star matvecs (row-major, float4) =====
        {
            const int gg = warp >> 2;
            const int t = tid & 127;
            const float* MT = gg ? g_M2 : g_M1;
            float* V2g = gg ? V2B : V2A;
            const float4* mr = reinterpret_cast<const float4*>(MT + t * 128);
            float acc = 0.f;
            #pragma unroll 8
            for (int d4 = 0; d4 < 32; d4++) {
                float4 mv = __ldg(&mr[d4]);
                float4 sv = *reinterpret_cast<const float4*>(&STAR[d4 * 4]);
                acc += mv.x * sv.x + mv.y * sv.y + mv.z * sv.z + mv.w * sv.w;
            }
            V2g[t] = acc;
        }

        // ===== e-logits: no Y tile — scale A-frags in regs per k =====
        float sel[4][4];
        #pragma unroll
        for (int nt = 0; nt < 4; nt++)
            #pragma unroll
            for (int q = 0; q < 4; q++) sel[nt][q] = NEG_BIG;

        for (int k = 0; k < 4; k++) {
            float ce[4][4];
            #pragma unroll
            for (int nt = 0; nt < 4; nt++)
                #pragma unroll
                for (int q = 0; q < 4; q++) ce[nt][q] = 0.f;
            #pragma unroll
            for (int kt = 0; kt < 8; kt++) {
                uint32_t fh[4], fl[4];
                LDSM4(fh, abase + kt * 32);
                LDSM4(fl, abase + THALF + kt * 32);
                uint4 sc = *reinterpret_cast<const uint4*>(
                    &AKT[((k * 8 + kt) * 4 + (lane & 3)) * 4]);
                #pragma unroll
                for (int q = 0; q < 4; q++) {
                    uint32_t uh = (q >= 2) ? sc.y : sc.x;
                    uint32_t ul = (q >= 2) ? sc.w : sc.z;
                    uint32_t p, r;
                    FMA16X2(p, fh[q], uh, Z16);
                    FMA16X2(r, fh[q], uh, p ^ 0x80008000u);   // exact residual
                    FMA16X2(r, fl[q], uh, r);
                    FMA16X2(fl[q], fh[q], ul, r);             // A'l
                    fh[q] = p;                                // A'h
                }
                #pragma unroll
                for (int nt = 0; nt < 4; nt++) {
                    uint32_t bh0, bh1, bl0, bl1;
                    uint32_t ba = xbbase + nt * (8 * TS) + kt * 32;
                    LDSM2(bh0, bh1, ba);
                    LDSM2(bl0, bl1, ba + THALF);
                    MMA16816(ce[nt][0], ce[nt][1], ce[nt][2], ce[nt][3], fh, bh0, bh1);
                    MMA16816(ce[nt][0], ce[nt][1], ce[nt][2], ce[nt][3], fh, bl0, bl1);
                    MMA16816(ce[nt][0], ce[nt][1], ce[nt][2], ce[nt][3], fl, bh0, bh1);
                }
            }
            int code = k + 1;
            #pragma unroll
            for (int nt = 0; nt < 4; nt++) {
                int j0 = N0 + nt * 8 + ((lane & 3) << 1);
                if (ADJ[i0 * 68 + j0] == code)
                    sel[nt][0] = (ce[nt][0] >= 0.f) ? ce[nt][0] : 0.2f * ce[nt][0];
                if (ADJ[i0 * 68 + j0 + 1] == code)
                    sel[nt][1] = (ce[nt][1] >= 0.f) ? ce[nt][1] : 0.2f * ce[nt][1];
                if (ADJ[(i0 + 8) * 68 + j0] == code)
                    sel[nt][2] = (ce[nt][2] >= 0.f) ? ce[nt][2] : 0.2f * ce[nt][2];
                if (ADJ[(i0 + 8) * 68 + j0 + 1] == code)
                    sel[nt][3] = (ce[nt][3] >= 0.f) ? ce[nt][3] : 0.2f * ce[nt][3];
            }
        }

        // ===== fragment softmax (named 64-thread barriers per mstrip pair) =====
        float m0 = NEG_BIG, m1 = NEG_BIG;
        #pragma unroll
        for (int nt = 0; nt < 4; nt++) {
            m0 = fmaxf(m0, fmaxf(sel[nt][0], sel[nt][1]));
            m1 = fmaxf(m1, fmaxf(sel[nt][2], sel[nt][3]));
        }
        m0 = fmaxf(m0, __shfl_xor_sync(0xffffffffu, m0, 1));
        m0 = fmaxf(m0, __shfl_xor_sync(0xffffffffu, m0, 2));
        m1 = fmaxf(m1, __shfl_xor_sync(0xffffffffu, m1, 1));
        m1 = fmaxf(m1, __shfl_xor_sync(0xffffffffu, m1, 2));
        if ((lane & 3) == 0) { PA[i0 * 2 + nhalf] = m0; PA[(i0 + 8) * 2 + nhalf] = m1; }
        asm volatile("bar.sync %0, 64;" :: "r"(1 + mstrip) : "memory");
        m0 = fmaxf(PA[i0 * 2], PA[i0 * 2 + 1]);
        m1 = fmaxf(PA[(i0 + 8) * 2], PA[(i0 + 8) * 2 + 1]);
        float s0 = 0.f, s1 = 0.f;
        #pragma unroll
        for (int nt = 0; nt < 4; nt++) {
            sel[nt][0] = __expf(sel[nt][0] - m0); s0 += sel[nt][0];
            sel[nt][1] = __expf(sel[nt][1] - m0); s0 += sel[nt][1];
            sel[nt][2] = __expf(sel[nt][2] - m1); s1 += sel[nt][2];
            sel[nt][3] = __expf(sel[nt][3] - m1); s1 += sel[nt][3];
        }
        s0 += __shfl_xor_sync(0xffffffffu, s0, 1);
        s0 += __shfl_xor_sync(0xffffffffu, s0, 2);
        s1 += __shfl_xor_sync(0xffffffffu, s1, 1);
        s1 += __shfl_xor_sync(0xffffffffu, s1, 2);
        if ((lane & 3) == 0) { PB[i0 * 2 + nhalf] = s0; PB[(i0 + 8) * 2 + nhalf] = s1; }
        asm volatile("bar.sync %0, 64;" :: "r"(1 + mstrip) : "memory");
        float inv0 = 1.f / (PB[i0 * 2] + PB[i0 * 2 + 1]);
        float inv1 = 1.f / (PB[(i0 + 8) * 2] + PB[(i0 + 8) * 2 + 1]);

        // ===== write ATT tile =====
        #pragma unroll
        for (int nt = 0; nt < 4; nt++) {
            int j0 = N0 + nt * 8 + ((lane & 3) << 1);
            uint32_t hi, lo;
            cvt_hilo(make_float2(sel[nt][0] * inv0, sel[nt][1] * inv0), hi, lo);
            int off = i0 * ATT_S + j0 * 2;
            *reinterpret_cast<uint32_t*>(YT + off)            = hi;
            *reinterpret_cast<uint32_t*>(YT + ATT_HALF + off) = lo;
            cvt_hilo(make_float2(sel[nt][2] * inv1, sel[nt][3] * inv1), hi, lo);
            off = (i0 + 8) * ATT_S + j0 * 2;
            *reinterpret_cast<uint32_t*>(YT + off)            = hi;
            *reinterpret_cast<uint32_t*>(YT + ATT_HALF + off) = lo;
        }
        __syncthreads();

        // ===== T = att @ S (A from ATT, B = X^T) =====
        {
            uint32_t aah[16], aal[16];
            uint32_t tabase = YH + (uint32_t)(R0 + (lane & 7) + ((m4 & 1) << 3)) * ATT_S
                            + ((m4 >> 1) << 4);
            #pragma unroll
            for (int kt = 0; kt < 4; kt++) {
                LDSM4(&aah[kt * 4], tabase + kt * 32);
                LDSM4(&aal[kt * 4], tabase + ATT_HALF + kt * 32);
            }
            const int N0d = nhalf * 64;
            float tc[8][4];
            #pragma unroll
            for (int nt = 0; nt < 8; nt++)
                #pragma unroll
                for (int q = 0; q < 4; q++) tc[nt][q] = 0.f;
            #pragma unroll
            for (int nt = 0; nt < 8; nt++) {
                #pragma unroll
                for (int kt = 0; kt < 4; kt++) {
                    uint32_t bh0, bh1, bl0, bl1;
                    uint32_t ba = XH + (uint32_t)(kt * 16 + lsel) * TS + (uint32_t)(N0d + nt * 8) * 2;
                    LDSM2T(bh0, bh1, ba);
                    LDSM2T(bl0, bl1, ba + THALF);
                    MMA16816(tc[nt][0], tc[nt][1], tc[nt][2], tc[nt][3], &aah[kt * 4], bh0, bh1);
                    MMA16816(tc[nt][0], tc[nt][1], tc[nt][2], tc[nt][3], &aah[kt * 4], bl0, bl1);
                    MMA16816(tc[nt][0], tc[nt][1], tc[nt][2], tc[nt][3], &aal[kt * 4], bh0, bh1);
                }
            }

            float pa0 = 0.f, pa1 = 0.f;
            #pragma unroll
            for (int nt = 0; nt < 8; nt++) {
                int d0 = N0d + nt * 8 + ((lane & 3) << 1);
                float2 va = *reinterpret_cast<const float2*>(&V2A[d0]);
                pa0 += tc[nt][0] * va.x + tc[nt][1] * va.y;
                pa1 += tc[nt][2] * va.x + tc[nt][3] * va.y;
            }
            pa0 += __shfl_xor_sync(0xffffffffu, pa0, 1);
            pa0 += __shfl_xor_sync(0xffffffffu, pa0, 2);
            pa1 += __shfl_xor_sync(0xffffffffu, pa1, 1);
            pa1 += __shfl_xor_sync(0xffffffffu, pa1, 2);
            if ((lane & 3) == 0) { PA[i0 * 2 + nhalf] = pa0; PA[(i0 + 8) * 2 + nhalf] = pa1; }
            __syncthreads();    // PA exchange + guards X writes below vs all X reads above
            float al0 = (PA[i0 * 2] + PA[i0 * 2 + 1]) * RSQ;
            float al1 = (PA[(i0 + 8) * 2] + PA[(i0 + 8) * 2 + 1]) * RSQ;

            float pb0 = 0.f, pb1 = 0.f;
            #pragma unroll
            for (int nt = 0; nt < 8; nt++) {
                int d0 = N0d + nt * 8 + ((lane & 3) << 1);
                float2 st = *reinterpret_cast<const float2*>(&STAR[d0]);
                float2 vb = *reinterpret_cast<const float2*>(&V2B[d0]);
                float n0x = (1.f - al0) * tc[nt][0] + al0 * st.x;
                float n0y = (1.f - al0) * tc[nt][1] + al0 * st.y;
                float n1x = (1.f - al1) * tc[nt][2] + al1 * st.x;
                float n1y = (1.f - al1) * tc[nt][3] + al1 * st.y;
                *reinterpret_cast<float2*>(&S[i0 * NPAD + d0])       = make_float2(n0x, n0y);
                *reinterpret_cast<float2*>(&S[(i0 + 8) * NPAD + d0]) = make_float2(n1x, n1y);
                uint32_t hi, lo;
                int off = i0 * TS + d0 * 2;
                cvt_hilo(make_float2(n0x, n0y), hi, lo);
                *reinterpret_cast<uint32_t*>(XT + off)         = hi;
                *reinterpret_cast<uint32_t*>(XT + THALF + off) = lo;
                off = (i0 + 8) * TS + d0 * 2;
                cvt_hilo(make_float2(n1x, n1y), hi, lo);
                *reinterpret_cast<uint32_t*>(XT + off)         = hi;
                *reinterpret_cast<uint32_t*>(XT + THALF + off) = lo;
                pb0 += n0x * vb.x + n0y * vb.y;
                pb1 += n1x * vb.x + n1y * vb.y;
            }
            pb0 += __shfl_xor_sync(0xffffffffu, pb0, 1);
            pb0 += __shfl_xor_sync(0xffffffffu, pb0, 2);
            pb1 += __shfl_xor_sync(0xffffffffu, pb1, 1);
            pb1 += __shfl_xor_sync(0xffffffffu, pb1, 2);
            if ((lane & 3) == 0) { PB[i0 * 2 + nhalf] = pb0; PB[(i0 + 8) * 2 + nhalf] = pb1; }
        }
        __syncthreads();

        if (warp == 0) {
            float b0 = (MS[lane] == 0.f)      ? __int_as_float(0xff800000)
                                              : (PB[lane * 2] + PB[lane * 2 + 1]) * RSQ;
            float b1 = (MS[lane + 32] == 0.f) ? __int_as_float(0xff800000)
                                              : (PB[(lane + 32) * 2] + PB[(lane + 32) * 2 + 1]) * RSQ;
            float m = fmaxf(b0, b1);
            #pragma unroll
            for (int o = 16; o > 0; o >>= 1) m = fmaxf(m, __shfl_xor_sync(0xffffffffu, m, o));
            float e0 = __expf(b0 - m), e1 = __expf(b1 - m);
            float sE = e0 + e1;
            #pragma unroll
            for (int o = 16; o > 0; o >>= 1) sE += __shfl_xor_sync(0xffffffffu, sE, o);
            float inv = 1.f / sE;
            BR[lane] = e0 * inv; BR[lane + 32] = e1 * inv;
        }
        __syncthreads();
        if (tid < 128) {
            float acc = 0.f;
            #pragma unroll 8
            for (int j = 0; j < 64; j++) acc += BR[j] * S[j * NPAD + tid];
            STAR[tid] = acc;
        }
        __syncthreads();
    }

    // ===== gate: C = cat(hidden,S) @ W^T =====
    {
        char* WT = YT;
        const uint32_t WTH = YH;
        const int N0g = nhalf * 64;
        float acc[8][4];
        #pragma unroll
        for (int nt = 0; nt < 8; nt++)
            #pragma unroll
            for (int q = 0; q < 4; q++) acc[nt][q] = 0.f;

        for (int chunk = 0; chunk < 4; chunk++) {
            const int c0 = chunk * 64;
            __syncthreads();
            for (int idx = tid; idx < 4096; idx += 256) {
                int o = idx >> 5, p = idx & 31;
                float2 w = __ldg(reinterpret_cast<const float2*>(&wlin[o * 256 + c0 + p * 2]));
                uint32_t hi, lo;
                cvt_hilo(w, hi, lo);
                *reinterpret_cast<uint32_t*>(WT + o * GWS + p * 4)          = hi;
                *reinterpret_cast<uint32_t*>(WT + GWHALF + o * GWS + p * 4) = lo;
            }
            __syncthreads();
            const bool fh2 = chunk < 2;
            const int cb = fh2 ? c0 : (c0 - 128);
            const int r0 = i0;
            #pragma unroll
            for (int kt = 0; kt < 4; kt++) {
                uint32_t fah[4], fal[4];
                if (fh2) {
                    int cc = cb + kt * 16 + ((lane & 3) << 1);
                    float2 x00 = __ldg(reinterpret_cast<const float2*>(&hg[r0 * 128 + cc]));
                    float2 x10 = __ldg(reinterpret_cast<const float2*>(&hg[(r0 + 8) * 128 + cc]));
                    float2 x01 = __ldg(reinterpret_cast<const float2*>(&hg[r0 * 128 + cc + 8]));
                    float2 x11 = __ldg(reinterpret_cast<const float2*>(&hg[(r0 + 8) * 128 + cc + 8]));
                    cvt_hilo(x00, fah[0], fal[0]);
                    cvt_hilo(x10, fah[1], fal[1]);
                    cvt_hilo(x01, fah[2], fal[2]);
                    cvt_hilo(x11, fah[3], fal[3]);
                } else {
                    uint32_t ab2 = abase + (uint32_t)(cb + kt * 16) * 2;
                    LDSM4(fah, ab2);
                    LDSM4(fal, ab2 + THALF);
                }
                uint32_t bb = WTH + (uint32_t)(N0g + (lsel & 7)) * GWS + ((lsel >> 3) << 4) + kt * 32;
                #pragma unroll
                for (int nt = 0; nt < 8; nt++) {
                    uint32_t bh0, bh1, bl0, bl1;
                    uint32_t ba = bb + nt * (8 * GWS);
                    LDSM2(bh0, bh1, ba);
                    LDSM2(bl0, bl1, ba + GWHALF);
                    MMA16816(acc[nt][0], acc[nt][1], acc[nt][2], acc[nt][3], fah, bh0, bh1);
                    MMA16816(acc[nt][0], acc[nt][1], acc[nt][2], acc[nt][3], fah, bl0, bl1);
                    MMA16816(acc[nt][0], acc[nt][1], acc[nt][2], acc[nt][3], fal, bh0, bh1);
                }
            }
        }

        float* ob = outp + (size_t)b * (NN * 128);
        const int r0 = i0;
        #pragma unroll
        for (int nt = 0; nt < 8; nt++) {
            int o0 = N0g + nt * 8 + ((lane & 3) << 1);
            float2 h0 = __ldg(reinterpret_cast<const float2*>(&hg[r0 * 128 + o0]));
            float2 s0v = *reinterpret_cast<const float2*>(&S[r0 * NPAD + o0]);
            float2 h1 = __ldg(reinterpret_cast<const float2*>(&hg[(r0 + 8) * 128 + o0]));
            float2 s1v = *reinterpret_cast<const float2*>(&S[(r0 + 8) * NPAD + o0]);
            float g00 = 1.f / (1.f + __expf(-acc[nt][0]));
            float g01 = 1.f / (1.f + __expf(-acc[nt][1]));
            float g10 = 1.f / (1.f + __expf(-acc[nt][2]));
            float g11 = 1.f / (1.f + __expf(-acc[nt][3]));
            float2 r0v, r1v;
            r0v.x = g00 * h0.x + (1.f - g00) * s0v.x;
            r0v.y = g01 * h0.y + (1.f - g01) * s0v.y;
            r1v.x = g10 * h1.x + (1.f - g10) * s1v.x;
            r1v.y = g11 * h1.y + (1.f - g11) * s1v.y;
            *reinterpret_cast<float2*>(&ob[r0 * 128 + o0])       = r0v;
            *reinterpret_cast<float2*>(&ob[(r0 + 8) * 128 + o0]) = r1v;
        }
    }
    if (tid < 128) starp[(size_t)b * 128 + tid] = STAR[tid];
}

extern "C" void kernel_launch(void* const* d_in, const int* in_sizes, int n_in,
                              void* d_out, int out_size) {
    float* outp  = (float*)d_out;
    float* starp = outp + (size_t)NB * NN * 128;

    prep_kernel<<<128, 256>>>((const float*)d_in[7], (const float*)d_in[8],
                              (const float*)d_in[9], (const float*)d_in[10]);
    cudaFuncSetAttribute(star_agg_kernel, cudaFuncAttributeMaxDynamicSharedMemorySize, SM_BYTES);
    star_agg_kernel<<<NB, 256, SM_BYTES>>>(
        (const float*)d_in[0], (const int*)d_in[1], (const float*)d_in[2],
        (const float*)d_in[3], (const float*)d_in[4], (const float*)d_in[5], (const float*)d_in[6],
        (const float*)d_in[11], outp, starp);
}